// round 14
// baseline (speedup 1.0000x reference)
#include <cuda_runtime.h>
#include <cuda_fp16.h>
#include <cstdint>
#include <cstddef>

// Problem constants
#define BJ   69632           // 4096*17 rows
#define NB   4096
#define NJ   17
#define ND   512
#define NH   8
#define NDK  64
#define NCHAINS 4
#define CH_ROWS (BJ / NCHAINS)   // 17408
#define CH_B    (NB / NCHAINS)   // 1024

// ---------------- device scratch ------------------------------------------------
__device__ __half g_src_h[(size_t)BJ * 512];
__device__ __half g_qkv  [(size_t)BJ * 1536];
__device__ __half g_o    [(size_t)BJ * 512];
__device__ __half g_x_h  [(size_t)BJ * 512];
__device__ __half g_u    [(size_t)BJ * 1024];
__device__ __half g_Wqkv[1536 * 512];
__device__ float  g_bqkv[1536];
__device__ __half g_Wo_t[512 * 512];
__device__ __half g_Wcat[512 * 1024];
__device__ float  g_A[NJ * NJ];

// ---------------- helpers -------------------------------------------------------
__device__ __forceinline__ uint32_t smem_u32(const void* p) {
    uint32_t a;
    asm("{ .reg .u64 t; cvta.to.shared.u64 t, %1; cvt.u32.u64 %0, t; }" : "=r"(a) : "l"(p));
    return a;
}
__device__ __forceinline__ void cp16(uint32_t saddr, const void* gptr) {
    asm volatile("cp.async.cg.shared.global [%0], [%1], 16;" :: "r"(saddr), "l"(gptr));
}
__device__ __forceinline__ void cp_commit() { asm volatile("cp.async.commit_group;" ::: "memory"); }
__device__ __forceinline__ void cp_wait1()  { asm volatile("cp.async.wait_group 1;" ::: "memory"); }
__device__ __forceinline__ void cp_wait0()  { asm volatile("cp.async.wait_group 0;" ::: "memory"); }

__device__ __forceinline__ void ldsm4(uint32_t* r, uint32_t addr) {
    asm volatile("ldmatrix.sync.aligned.m8n8.x4.shared.b16 {%0,%1,%2,%3}, [%4];"
        : "=r"(r[0]), "=r"(r[1]), "=r"(r[2]), "=r"(r[3]) : "r"(addr));
}
__device__ __forceinline__ void mma_f16(float* d, const uint32_t* a, const uint32_t* b) {
    asm volatile(
        "mma.sync.aligned.m16n8k16.row.col.f32.f16.f16.f32 "
        "{%0,%1,%2,%3}, {%4,%5,%6,%7}, {%8,%9}, {%0,%1,%2,%3};"
        : "+f"(d[0]), "+f"(d[1]), "+f"(d[2]), "+f"(d[3])
        : "r"(a[0]), "r"(a[1]), "r"(a[2]), "r"(a[3]), "r"(b[0]), "r"(b[1]));
}

// ================= fp16 mma.sync GEMM ===========================================
#define STAGE_BYTES 32768
#define GEMM_SMEM   (3 * STAGE_BYTES)

__global__ __launch_bounds__(256, 2) void tc_gemm(const __half* __restrict__ A,
                                                  const __half* __restrict__ Bt,
                                                  const float* __restrict__ bias,
                                                  __half* __restrict__ C, int N) {
    extern __shared__ char smem[];
    const uint32_t sb = smem_u32(smem);
    const int tid  = threadIdx.x;
    const int lane = tid & 31;
    const int wid  = tid >> 5;
    const int warp_m = (wid & 1) * 64;
    const int warp_n = (wid >> 1) * 32;
    const int l7 = lane & 7;
    const int a_row_base = warp_m + l7 + ((lane & 8) ? 8 : 0);
    const int a_cc_add = (lane & 16) ? 1 : 0;
    const int b_row_base = warp_n + l7 + ((lane & 16) ? 8 : 0);
    const int b_cc_add = (lane & 8) ? 1 : 0;

    const __half* Abase = A  + (size_t)blockIdx.y * 128 * 512;
    const __half* Bbase = Bt + (size_t)blockIdx.x * 128 * 512;

    auto issue = [&](int t) {
        const int buf = t % 3;
        const uint32_t sA = sb + buf * STAGE_BYTES;
        const uint32_t sB = sA + 16384;
        const __half* Ab = Abase + t * 64;
        const __half* Bb = Bbase + t * 64;
        #pragma unroll
        for (int ll = 0; ll < 4; ++ll) {
            int id = tid + ll * 256, row = id >> 3, cc = id & 7;
            cp16(sA + row * 128 + ((cc ^ (row & 7)) << 4), Ab + (size_t)row * 512 + cc * 8);
        }
        #pragma unroll
        for (int ll = 0; ll < 4; ++ll) {
            int id = tid + ll * 256, row = id >> 3, cc = id & 7;
            cp16(sB + row * 128 + ((cc ^ (row & 7)) << 4), Bb + (size_t)row * 512 + cc * 8);
        }
        cp_commit();
    };

    float acc[4][4][4];
    #pragma unroll
    for (int i = 0; i < 4; ++i)
        #pragma unroll
        for (int j = 0; j < 4; ++j)
            #pragma unroll
            for (int q = 0; q < 4; ++q) acc[i][j][q] = 0.f;

    issue(0);
    issue(1);

    #pragma unroll 1
    for (int t = 0; t < 8; ++t) {
        if (t < 7) cp_wait1(); else cp_wait0();
        __syncthreads();
        if (t + 2 < 8) issue(t + 2);

        const int buf = t % 3;
        const uint32_t sA = sb + buf * STAGE_BYTES;
        const uint32_t sB = sA + 16384;

        #pragma unroll
        for (int q = 0; q < 4; ++q) {
            const int kc = 2 * q;
            uint32_t af[4][4], bf[2][4];
            #pragma unroll
            for (int i = 0; i < 4; ++i)
                ldsm4(af[i], sA + (uint32_t)(a_row_base + i * 16) * 128 +
                              (uint32_t)(((kc + a_cc_add) ^ l7) << 4));
            #pragma unroll
            for (int j2 = 0; j2 < 2; ++j2)
                ldsm4(bf[j2], sB + (uint32_t)(b_row_base + j2 * 16) * 128 +
                               (uint32_t)(((kc + b_cc_add) ^ l7) << 4));
            #pragma unroll
            for (int i = 0; i < 4; ++i)
                #pragma unroll
                for (int j = 0; j < 4; ++j)
                    mma_f16(acc[i][j], af[i], &bf[j >> 1][(j & 1) * 2]);
        }
    }

    const size_t rowBase = (size_t)blockIdx.y * 128 + warp_m + (lane >> 2);
    const int colBase = blockIdx.x * 128 + warp_n + (lane & 3) * 2;
    #pragma unroll
    for (int i = 0; i < 4; ++i) {
        #pragma unroll
        for (int j = 0; j < 4; ++j) {
            size_t m0 = rowBase + i * 16;
            int n0 = colBase + j * 8;
            float b0 = bias[n0], b1 = bias[n0 + 1];
            *(__half2*)(C + m0 * (size_t)N + n0) =
                __floats2half2_rn(acc[i][j][0] + b0, acc[i][j][1] + b1);
            *(__half2*)(C + (m0 + 8) * (size_t)N + n0) =
                __floats2half2_rn(acc[i][j][2] + b0, acc[i][j][3] + b1);
        }
    }
}

// ===== fused GEMM + bias + residual + LayerNorm (full 512-wide rows) ============
#define LNG_STAGE (8192 + 65536)
#define LNG_SMEM  (3 * LNG_STAGE)

template<int NCHUNK, bool RES_HALF, bool OUT_HALF>
__global__ __launch_bounds__(512) void ln_gemm_t(const __half* __restrict__ A,
                                                 const __half* __restrict__ Bt,
                                                 const float* __restrict__ bias,
                                                 const void* __restrict__ resid,
                                                 const float* __restrict__ gam,
                                                 const float* __restrict__ bet,
                                                 void* __restrict__ outp) {
    constexpr int K = NCHUNK * 64;
    extern __shared__ char smem[];
    const uint32_t sb = smem_u32(smem);
    const int tid  = threadIdx.x;
    const int lane = tid & 31;
    const int wid  = tid >> 5;
    const int warp_m = (wid & 1) * 32;
    const int wid_n  = wid >> 1;
    const int warp_n = wid_n * 64;
    const int l7 = lane & 7;
    const int a_row_base = warp_m + l7 + ((lane & 8) ? 8 : 0);
    const int a_cc_add = (lane & 16) ? 1 : 0;
    const int b_row_base = warp_n + l7 + ((lane & 16) ? 8 : 0);
    const int b_cc_add = (lane & 8) ? 1 : 0;

    const size_t rowBlk = (size_t)blockIdx.x * 64;
    const __half* Abase = A + rowBlk * K;

    auto issue = [&](int t) {
        const int buf = t % 3;
        const uint32_t sA = sb + buf * LNG_STAGE;
        const uint32_t sB = sA + 8192;
        const __half* Ab = Abase + t * 64;
        const __half* Bb = Bt + t * 64;
        {
            int row = tid >> 3, cc = tid & 7;
            cp16(sA + row * 128 + ((cc ^ (row & 7)) << 4), Ab + (size_t)row * K + cc * 8);
        }
        #pragma unroll
        for (int ll = 0; ll < 8; ++ll) {
            int id = tid + ll * 512, row = id >> 3, cc = id & 7;
            cp16(sB + row * 128 + ((cc ^ (row & 7)) << 4), Bb + (size_t)row * K + cc * 8);
        }
        cp_commit();
    };

    float acc[2][8][4];
    #pragma unroll
    for (int i = 0; i < 2; ++i)
        #pragma unroll
        for (int j = 0; j < 8; ++j)
            #pragma unroll
            for (int q = 0; q < 4; ++q) acc[i][j][q] = 0.f;

    issue(0);
    issue(1);

    #pragma unroll 1
    for (int t = 0; t < NCHUNK; ++t) {
        if (t < NCHUNK - 1) cp_wait1(); else cp_wait0();
        __syncthreads();
        if (t + 2 < NCHUNK) issue(t + 2);

        const int buf = t % 3;
        const uint32_t sA = sb + buf * LNG_STAGE;
        const uint32_t sB = sA + 8192;

        #pragma unroll
        for (int q = 0; q < 4; ++q) {
            const int kc = 2 * q;
            uint32_t af[2][4], bf[4][4];
            #pragma unroll
            for (int i = 0; i < 2; ++i)
                ldsm4(af[i], sA + (uint32_t)(a_row_base + i * 16) * 128 +
                              (uint32_t)(((kc + a_cc_add) ^ l7) << 4));
            #pragma unroll
            for (int j2 = 0; j2 < 4; ++j2)
                ldsm4(bf[j2], sB + (uint32_t)(b_row_base + j2 * 16) * 128 +
                               (uint32_t)(((kc + b_cc_add) ^ l7) << 4));
            #pragma unroll
            for (int i = 0; i < 2; ++i)
                #pragma unroll
                for (int j = 0; j < 8; ++j)
                    mma_f16(acc[i][j], af[i], &bf[j >> 1][(j & 1) * 2]);
        }
    }
    __syncthreads();

    float2* red  = (float2*)smem;
    float2* stat = (float2*)(smem + 4096);
    const int rq = lane >> 2;
    const int cq = (lane & 3) * 2;

    #pragma unroll
    for (int i = 0; i < 2; ++i) {
        #pragma unroll
        for (int h2 = 0; h2 < 2; ++h2) {
            int row_local = warp_m + i * 16 + h2 * 8 + rq;
            size_t grow = (rowBlk + row_local) * 512;
            float s = 0.f, ss = 0.f;
            #pragma unroll
            for (int j = 0; j < 8; ++j) {
                int col = warp_n + cq + j * 8;
                float2 sv;
                if (RES_HALF)
                    sv = __half22float2(*(const __half2*)((const __half*)resid + grow + col));
                else
                    sv = *(const float2*)((const float*)resid + grow + col);
                float v0 = acc[i][j][h2 * 2 + 0] + bias[col]     + sv.x;
                float v1 = acc[i][j][h2 * 2 + 1] + bias[col + 1] + sv.y;
                acc[i][j][h2 * 2 + 0] = v0;
                acc[i][j][h2 * 2 + 1] = v1;
                s += v0 + v1;
                ss = fmaf(v0, v0, ss); ss = fmaf(v1, v1, ss);
            }
            s  += __shfl_xor_sync(0xffffffffu, s, 1);  s  += __shfl_xor_sync(0xffffffffu, s, 2);
            ss += __shfl_xor_sync(0xffffffffu, ss, 1); ss += __shfl_xor_sync(0xffffffffu, ss, 2);
            if ((lane & 3) == 0) red[row_local * 8 + wid_n] = make_float2(s, ss);
        }
    }
    __syncthreads();
    if (tid < 64) {
        float s = 0.f, ss = 0.f;
        #pragma unroll
        for (int w = 0; w < 8; ++w) {
            float2 v = red[tid * 8 + w];
            s += v.x; ss += v.y;
        }
        float mean = s * (1.0f / 512.0f);
        float var  = ss * (1.0f / 512.0f) - mean * mean;
        stat[tid] = make_float2(mean, rsqrtf(var + 1e-5f));
    }
    __syncthreads();
    #pragma unroll
    for (int i = 0; i < 2; ++i) {
        #pragma unroll
        for (int h2 = 0; h2 < 2; ++h2) {
            int row_local = warp_m + i * 16 + h2 * 8 + rq;
            float2 st = stat[row_local];
            size_t grow = (rowBlk + row_local) * 512;
            #pragma unroll
            for (int j = 0; j < 8; ++j) {
                int col = warp_n + cq + j * 8;
                float y0 = (acc[i][j][h2 * 2 + 0] - st.x) * st.y * gam[col]     + bet[col];
                float y1 = (acc[i][j][h2 * 2 + 1] - st.x) * st.y * gam[col + 1] + bet[col + 1];
                if (OUT_HALF)
                    *(__half2*)((__half*)outp + grow + col) = __floats2half2_rn(y0, y1);
                else
                    *(float2*)((float*)outp + grow + col) = make_float2(y0, y1);
            }
        }
    }
}

// ---------------- src -> half (float4 per thread, offset form) ------------------
__global__ void conv_src(const float* __restrict__ src, __half* __restrict__ dst, int n4) {
    int idx = blockIdx.x * blockDim.x + threadIdx.x;
    if (idx >= n4) return;
    float4 v = *(const float4*)(src + (size_t)idx * 4);
    __half2 a = __floats2half2_rn(v.x, v.y);
    __half2 b = __floats2half2_rn(v.z, v.w);
    uint2 w;
    w.x = *(uint32_t*)&a;
    w.y = *(uint32_t*)&b;
    *(uint2*)(dst + (size_t)idx * 4) = w;
}

// ---------------- weight packing ------------------------------------------------
__global__ void pack_qkv_w(const float* __restrict__ Wq, const float* __restrict__ Wk,
                           const float* __restrict__ Wv, const float* __restrict__ bq,
                           const float* __restrict__ bk, const float* __restrict__ bv) {
    int idx = blockIdx.x * blockDim.x + threadIdx.x;
    if (idx >= 512 * 1536) return;
    int d = idx / 1536, cc2 = idx % 1536;
    int sel = cc2 / 512, cc = cc2 % 512;
    int h = cc / 64, e = cc % 64;
    const float* W = (sel == 0) ? Wq : (sel == 1) ? Wk : Wv;
    g_Wqkv[(size_t)cc2 * 512 + d] = __float2half_rn(W[((size_t)h * 512 + d) * 64 + e]);
    if (d == 0) {
        const float* bb = (sel == 0) ? bq : (sel == 1) ? bk : bv;
        g_bqkv[cc2] = bb[cc];
    }
}

__global__ void pack_wo(const float* __restrict__ Wo) {
    int idx = blockIdx.x * blockDim.x + threadIdx.x;
    if (idx >= 512 * 512) return;
    int n = idx / 512, k = idx % 512;
    g_Wo_t[idx] = __float2half_rn(Wo[(size_t)k * 512 + n]);
}

__global__ void pack_wcat(const float* __restrict__ Wgcn) {
    int idx = blockIdx.x * blockDim.x + threadIdx.x;
    if (idx >= 512 * 1024) return;
    int n = idx / 1024, k = idx % 1024;
    float v;
    if (k < 512) v = Wgcn[(size_t)k * 512 + n] - Wgcn[262144 + (size_t)k * 512 + n];
    else         v = Wgcn[262144 + (size_t)(k - 512) * 512 + n];
    g_Wcat[idx] = __float2half_rn(v);
}

// ---------------- adjacency softmax ---------------------------------------------
__global__ void build_A(const int* __restrict__ rows, const int* __restrict__ cols,
                        const float* __restrict__ e, int nnz) {
    __shared__ float lg[NJ][NJ];
    int tid = threadIdx.x;
    if (tid < NJ * NJ) lg[tid / NJ][tid % NJ] = -9e15f;
    __syncthreads();
    if (tid < nnz) lg[rows[tid]][cols[tid]] = e[tid];
    __syncthreads();
    if (tid < NJ) {
        float m = -9e15f;
        #pragma unroll
        for (int k = 0; k < NJ; k++) m = fmaxf(m, lg[tid][k]);
        float ex[NJ]; float s = 0.f;
        #pragma unroll
        for (int k = 0; k < NJ; k++) { ex[k] = __expf(lg[tid][k] - m); s += ex[k]; }
        float inv = 1.0f / s;
        #pragma unroll
        for (int k = 0; k < NJ; k++) g_A[tid * NJ + k] = ex[k] * inv;
    }
}

// ---------------- attention: one block per batch, 9 warps, half2 smem -----------
#define QLD 257
#define KLD 259
#define VLD 257
#define ATTN_SMEM (NJ * (QLD + KLD + VLD) * 4)

__global__ __launch_bounds__(288) void attn_kernel(const __half* __restrict__ qkv,
                                                   __half* __restrict__ o) {
    extern __shared__ uint32_t sm2[];
    uint32_t* qs = sm2;
    uint32_t* ks = qs + NJ * QLD;
    uint32_t* vs = ks + NJ * KLD;

    int b = blockIdx.x;
    int tid = threadIdx.x;
    const uint32_t* base = (const uint32_t*)(qkv + (size_t)b * NJ * 1536);

    for (int i = tid; i < NJ * 768; i += 288) {
        int row = i / 768, c = i % 768;
        uint32_t w = base[row * 768 + c];
        if (c < 256)      qs[row * QLD + c]        = w;
        else if (c < 512) ks[row * KLD + (c - 256)] = w;
        else              vs[row * VLD + (c - 512)] = w;
    }
    __syncthreads();

    int wrp = tid >> 5, lane = tid & 31;
    #pragma unroll 1
    for (int rep = 0; rep < 2; ++rep) {
        int j = wrp + rep * 9;
        if (j >= NJ) break;
        __half* orow = o + ((size_t)(b * NJ + j)) * 512;

        #pragma unroll 1
        for (int h = 0; h < NH; ++h) {
            const int hw = h * 32;
            float s = -1e30f;
            if (lane < NJ) {
                const uint32_t* qp = qs + j * QLD + hw;
                const uint32_t* kp = ks + lane * KLD + hw;
                float acc = 0.f;
                #pragma unroll
                for (int e = 0; e < 32; ++e) {
                    float2 qv = __half22float2(*(const __half2*)&qp[e]);
                    float2 kv = __half22float2(*(const __half2*)&kp[e]);
                    acc = fmaf(qv.x, kv.x, fmaf(qv.y, kv.y, acc));
                }
                s = acc * 0.125f;
            }
            float m = s;
            #pragma unroll
            for (int off = 16; off; off >>= 1) m = fmaxf(m, __shfl_xor_sync(0xffffffffu, m, off));
            float p = (lane < NJ) ? __expf(s - m) : 0.f;
            float sum = p;
            #pragma unroll
            for (int off = 16; off; off >>= 1) sum += __shfl_xor_sync(0xffffffffu, sum, off);
            p *= (1.0f / sum);

            const int wsel = lane & 1;
            const int widx = hw + (lane >> 1);
            float o0 = 0.f, o1 = 0.f;
            #pragma unroll
            for (int k = 0; k < NJ; ++k) {
                float pk = __shfl_sync(0xffffffffu, p, k);
                __half2 w0 = *(__half2*)&vs[k * VLD + widx];
                __half2 w1 = *(__half2*)&vs[k * VLD + widx + 16];
                float v0 = wsel ? __high2float(w0) : __low2float(w0);
                float v1 = wsel ? __high2float(w1) : __low2float(w1);
                o0 = fmaf(pk, v0, o0);
                o1 = fmaf(pk, v1, o1);
            }
            orow[h * 64 + lane]      = __float2half_rn(o0);
            orow[h * 64 + lane + 32] = __float2half_rn(o1);
        }
    }
}

// ---------------- premix: u_j = [A_jj*x_j ; sum_k A_jk*x_k] ---------------------
__global__ __launch_bounds__(544) void premix(const __half* __restrict__ x,
                                              __half* __restrict__ u) {
    int b = blockIdx.x;
    __shared__ float xs[NJ][512];
    __shared__ float Arow[NJ][NJ];
    __shared__ float Ad[NJ];
    int tid = threadIdx.y * 32 + threadIdx.x;
    for (int i = tid; i < NJ * 256; i += 544) {
        int k = i >> 8, e2 = i & 255;
        float2 v = __half22float2(*(const __half2*)(x + ((size_t)(b * NJ + k)) * 512 + e2 * 2));
        xs[k][e2 * 2] = v.x; xs[k][e2 * 2 + 1] = v.y;
    }
    if (tid < NJ * NJ) {
        int j = tid / NJ, k = tid % NJ;
        float a = g_A[tid];
        Arow[j][k] = a;
        if (j == k) Ad[j] = a;
    }
    __syncthreads();

    int j = threadIdx.y, lane = threadIdx.x;
    __half* ur = u + ((size_t)(b * NJ + j)) * 1024;
    float adiag = Ad[j];
    #pragma unroll
    for (int t = 0; t < 16; t++) {
        int d = lane + (t << 5);
        float z = 0.f;
        #pragma unroll
        for (int k = 0; k < NJ; k++) z = fmaf(Arow[j][k], xs[k][d], z);
        ur[d]       = __float2half_rn(adiag * xs[j][d]);
        ur[512 + d] = __float2half_rn(z);
    }
}

// ---------------- host launcher --------------------------------------------------
extern "C" void kernel_launch(void* const* d_in, const int* in_sizes, int n_in,
                              void* d_out, int out_size) {
    const float* src   = (const float*)d_in[0];
    const float* Wq    = (const float*)d_in[1];
    const float* bq    = (const float*)d_in[2];
    const float* Wk    = (const float*)d_in[3];
    const float* bk    = (const float*)d_in[4];
    const float* Wv    = (const float*)d_in[5];
    const float* bv    = (const float*)d_in[6];
    const float* Wo    = (const float*)d_in[7];
    const float* bo    = (const float*)d_in[8];
    const float* ln1_g = (const float*)d_in[9];
    const float* ln1_b = (const float*)d_in[10];
    const float* Wgcn  = (const float*)d_in[11];
    const float* egcn  = (const float*)d_in[12];
    const float* bgcn  = (const float*)d_in[13];
    const float* ln2_g = (const float*)d_in[14];
    const float* ln2_b = (const float*)d_in[15];
    const int*   mrows = (const int*)d_in[16];
    const int*   mcols = (const int*)d_in[17];
    int nnz = in_sizes[16];
    float* out = (float*)d_out;

    __half *p_srch, *p_qkv, *p_o, *p_xh, *p_u, *p_Wqkv, *p_Wot, *p_Wcat;
    float *p_bqkv;
    cudaGetSymbolAddress((void**)&p_srch, g_src_h);
    cudaGetSymbolAddress((void**)&p_qkv,  g_qkv);
    cudaGetSymbolAddress((void**)&p_o,    g_o);
    cudaGetSymbolAddress((void**)&p_xh,   g_x_h);
    cudaGetSymbolAddress((void**)&p_u,    g_u);
    cudaGetSymbolAddress((void**)&p_Wqkv, g_Wqkv);
    cudaGetSymbolAddress((void**)&p_bqkv, g_bqkv);
    cudaGetSymbolAddress((void**)&p_Wot,  g_Wo_t);
    cudaGetSymbolAddress((void**)&p_Wcat, g_Wcat);

    // Exactly 3 created streams (R12's passing budget). Side streams double as
    // chain streams after their pack work completes.
    static cudaStream_t s_side = nullptr, s_side2 = nullptr, s_c1 = nullptr;
    static cudaEvent_t e_fork = nullptr, e_join = nullptr, e_join2 = nullptr;
    static cudaEvent_t e_f1 = nullptr, e_f2 = nullptr, e_f3 = nullptr;
    if (!s_side) {
        cudaStreamCreateWithFlags(&s_side, cudaStreamNonBlocking);
        cudaStreamCreateWithFlags(&s_side2, cudaStreamNonBlocking);
        cudaStreamCreateWithFlags(&s_c1, cudaStreamNonBlocking);
        cudaEventCreateWithFlags(&e_fork, cudaEventDisableTiming);
        cudaEventCreateWithFlags(&e_join, cudaEventDisableTiming);
        cudaEventCreateWithFlags(&e_join2, cudaEventDisableTiming);
        cudaEventCreateWithFlags(&e_f1, cudaEventDisableTiming);
        cudaEventCreateWithFlags(&e_f2, cudaEventDisableTiming);
        cudaEventCreateWithFlags(&e_f3, cudaEventDisableTiming);
        cudaFuncSetAttribute(tc_gemm, cudaFuncAttributeMaxDynamicSharedMemorySize, GEMM_SMEM);
        cudaFuncSetAttribute(ln_gemm_t<8,  false, true >, cudaFuncAttributeMaxDynamicSharedMemorySize, LNG_SMEM);
        cudaFuncSetAttribute(ln_gemm_t<16, true,  false>, cudaFuncAttributeMaxDynamicSharedMemorySize, LNG_SMEM);
        cudaFuncSetAttribute(attn_kernel, cudaFuncAttributeMaxDynamicSharedMemorySize, ATTN_SMEM);
    }

    // ---- fork: packing on the two side streams
    cudaEventRecord(e_fork, 0);
    cudaStreamWaitEvent(s_side, e_fork, 0);
    cudaStreamWaitEvent(s_side2, e_fork, 0);
    cudaStreamWaitEvent(s_c1, e_fork, 0);
    pack_wo<<<(512 * 512 + 255) / 256, 256, 0, s_side>>>(Wo);
    pack_wcat<<<(512 * 1024 + 255) / 256, 256, 0, s_side>>>(Wgcn);
    build_A<<<1, 512, 0, s_side>>>(mrows, mcols, egcn, nnz);
    cudaEventRecord(e_join, s_side);

    pack_qkv_w<<<(512 * 1536 + 255) / 256, 256, 0, s_side2>>>(Wq, Wk, Wv, bq, bk, bv);
    cudaEventRecord(e_join2, s_side2);

    // Chain->stream map: 0->default, 1->s_c1, 2->s_side, 3->s_side2.
    // Streams 2/3 run their pack work first (program order); all chains wait
    // e_join2 before the QKV GEMM and e_join before LNG1.
    cudaStream_t chst[NCHAINS] = { (cudaStream_t)0, s_c1, s_side, s_side2 };

    for (int c = 0; c < NCHAINS; ++c) {
        cudaStream_t st = chst[c];
        const size_t r0 = (size_t)c * CH_ROWS;
        const float*  srcH  = src    + r0 * 512;
        __half*       srchH = p_srch + r0 * 512;
        __half*       qkvH  = p_qkv  + r0 * 1536;
        __half*       oH    = p_o    + r0 * 512;
        __half*       xhH   = p_xh   + r0 * 512;
        __half*       uH    = p_u    + r0 * 1024;
        float*        outH  = out    + r0 * 512;

        conv_src<<<(CH_ROWS * 128 + 255) / 256, 256, 0, st>>>(srcH, srchH, CH_ROWS * 128);
        if (st != s_side2) cudaStreamWaitEvent(st, e_join2, 0);
        tc_gemm<<<dim3(1536 / 128, CH_ROWS / 128), 256, GEMM_SMEM, st>>>(srchH, p_Wqkv, p_bqkv, qkvH, 1536);
        attn_kernel<<<CH_B, 288, ATTN_SMEM, st>>>(qkvH, oH);
        if (st != s_side) cudaStreamWaitEvent(st, e_join, 0);
        ln_gemm_t<8, false, true><<<CH_ROWS / 64, 512, LNG_SMEM, st>>>(oH, p_Wot, bo, srcH, ln1_g, ln1_b, xhH);
        premix<<<CH_B, dim3(32, NJ), 0, st>>>(xhH, uH);
        ln_gemm_t<16, true, false><<<CH_ROWS / 64, 512, LNG_SMEM, st>>>(uH, p_Wcat, bgcn, xhH, ln2_g, ln2_b, outH);
    }

    // ---- join the three side chains back into the default stream
    cudaEventRecord(e_f1, s_c1);
    cudaEventRecord(e_f2, s_side);
    cudaEventRecord(e_f3, s_side2);
    cudaStreamWaitEvent(0, e_f1, 0);
    cudaStreamWaitEvent(0, e_f2, 0);
    cudaStreamWaitEvent(0, e_f3, 0);
}

// round 15
// speedup vs baseline: 1.1757x; 1.1757x over previous
#include <cuda_runtime.h>
#include <cuda_fp16.h>
#include <cstdint>
#include <cstddef>

// Problem constants
#define BJ   69632           // 4096*17 rows
#define NB   4096
#define NJ   17
#define ND   512
#define NH   8
#define NDK  64
#define NCHAINS 4
#define CH_ROWS (BJ / NCHAINS)   // 17408
#define CH_B    (NB / NCHAINS)   // 1024

// ---------------- device scratch ------------------------------------------------
__device__ __half g_src_h[(size_t)BJ * 512];
__device__ __half g_qkv  [(size_t)BJ * 1536];
__device__ __half g_o    [(size_t)BJ * 512];
__device__ __half g_x_h  [(size_t)BJ * 512];
__device__ __half g_u    [(size_t)BJ * 1024];
__device__ __half g_Wqkv[1536 * 512];
__device__ float  g_bqkv[1536];
__device__ __half g_Wo_t[512 * 512];
__device__ __half g_Wcat[512 * 1024];
__device__ float  g_A[NJ * NJ];

// ---------------- helpers -------------------------------------------------------
__device__ __forceinline__ uint32_t smem_u32(const void* p) {
    uint32_t a;
    asm("{ .reg .u64 t; cvta.to.shared.u64 t, %1; cvt.u32.u64 %0, t; }" : "=r"(a) : "l"(p));
    return a;
}
__device__ __forceinline__ void cp16(uint32_t saddr, const void* gptr) {
    asm volatile("cp.async.cg.shared.global [%0], [%1], 16;" :: "r"(saddr), "l"(gptr));
}
__device__ __forceinline__ void cp_commit() { asm volatile("cp.async.commit_group;" ::: "memory"); }
__device__ __forceinline__ void cp_wait1()  { asm volatile("cp.async.wait_group 1;" ::: "memory"); }
__device__ __forceinline__ void cp_wait0()  { asm volatile("cp.async.wait_group 0;" ::: "memory"); }

__device__ __forceinline__ void ldsm4(uint32_t* r, uint32_t addr) {
    asm volatile("ldmatrix.sync.aligned.m8n8.x4.shared.b16 {%0,%1,%2,%3}, [%4];"
        : "=r"(r[0]), "=r"(r[1]), "=r"(r[2]), "=r"(r[3]) : "r"(addr));
}
__device__ __forceinline__ void ldsm2(uint32_t* r, uint32_t addr) {
    asm volatile("ldmatrix.sync.aligned.m8n8.x2.shared.b16 {%0,%1}, [%2];"
        : "=r"(r[0]), "=r"(r[1]) : "r"(addr));
}
__device__ __forceinline__ void ldsm4t(uint32_t* r, uint32_t addr) {
    asm volatile("ldmatrix.sync.aligned.m8n8.x4.trans.shared.b16 {%0,%1,%2,%3}, [%4];"
        : "=r"(r[0]), "=r"(r[1]), "=r"(r[2]), "=r"(r[3]) : "r"(addr));
}
__device__ __forceinline__ void mma_f16(float* d, const uint32_t* a, const uint32_t* b) {
    asm volatile(
        "mma.sync.aligned.m16n8k16.row.col.f32.f16.f16.f32 "
        "{%0,%1,%2,%3}, {%4,%5,%6,%7}, {%8,%9}, {%0,%1,%2,%3};"
        : "+f"(d[0]), "+f"(d[1]), "+f"(d[2]), "+f"(d[3])
        : "r"(a[0]), "r"(a[1]), "r"(a[2]), "r"(a[3]), "r"(b[0]), "r"(b[1]));
}

// ================= fp16 mma.sync GEMM ===========================================
#define STAGE_BYTES 32768
#define GEMM_SMEM   (3 * STAGE_BYTES)

__global__ __launch_bounds__(256, 2) void tc_gemm(const __half* __restrict__ A,
                                                  const __half* __restrict__ Bt,
                                                  const float* __restrict__ bias,
                                                  __half* __restrict__ C, int N) {
    extern __shared__ char smem[];
    const uint32_t sb = smem_u32(smem);
    const int tid  = threadIdx.x;
    const int lane = tid & 31;
    const int wid  = tid >> 5;
    const int warp_m = (wid & 1) * 64;
    const int warp_n = (wid >> 1) * 32;
    const int l7 = lane & 7;
    const int a_row_base = warp_m + l7 + ((lane & 8) ? 8 : 0);
    const int a_cc_add = (lane & 16) ? 1 : 0;
    const int b_row_base = warp_n + l7 + ((lane & 16) ? 8 : 0);
    const int b_cc_add = (lane & 8) ? 1 : 0;

    const __half* Abase = A  + (size_t)blockIdx.y * 128 * 512;
    const __half* Bbase = Bt + (size_t)blockIdx.x * 128 * 512;

    auto issue = [&](int t) {
        const int buf = t % 3;
        const uint32_t sA = sb + buf * STAGE_BYTES;
        const uint32_t sB = sA + 16384;
        const __half* Ab = Abase + t * 64;
        const __half* Bb = Bbase + t * 64;
        #pragma unroll
        for (int ll = 0; ll < 4; ++ll) {
            int id = tid + ll * 256, row = id >> 3, cc = id & 7;
            cp16(sA + row * 128 + ((cc ^ (row & 7)) << 4), Ab + (size_t)row * 512 + cc * 8);
        }
        #pragma unroll
        for (int ll = 0; ll < 4; ++ll) {
            int id = tid + ll * 256, row = id >> 3, cc = id & 7;
            cp16(sB + row * 128 + ((cc ^ (row & 7)) << 4), Bb + (size_t)row * 512 + cc * 8);
        }
        cp_commit();
    };

    float acc[4][4][4];
    #pragma unroll
    for (int i = 0; i < 4; ++i)
        #pragma unroll
        for (int j = 0; j < 4; ++j)
            #pragma unroll
            for (int q = 0; q < 4; ++q) acc[i][j][q] = 0.f;

    issue(0);
    issue(1);

    #pragma unroll 1
    for (int t = 0; t < 8; ++t) {
        if (t < 7) cp_wait1(); else cp_wait0();
        __syncthreads();
        if (t + 2 < 8) issue(t + 2);

        const int buf = t % 3;
        const uint32_t sA = sb + buf * STAGE_BYTES;
        const uint32_t sB = sA + 16384;

        #pragma unroll
        for (int q = 0; q < 4; ++q) {
            const int kc = 2 * q;
            uint32_t af[4][4], bf[2][4];
            #pragma unroll
            for (int i = 0; i < 4; ++i)
                ldsm4(af[i], sA + (uint32_t)(a_row_base + i * 16) * 128 +
                              (uint32_t)(((kc + a_cc_add) ^ l7) << 4));
            #pragma unroll
            for (int j2 = 0; j2 < 2; ++j2)
                ldsm4(bf[j2], sB + (uint32_t)(b_row_base + j2 * 16) * 128 +
                               (uint32_t)(((kc + b_cc_add) ^ l7) << 4));
            #pragma unroll
            for (int i = 0; i < 4; ++i)
                #pragma unroll
                for (int j = 0; j < 4; ++j)
                    mma_f16(acc[i][j], af[i], &bf[j >> 1][(j & 1) * 2]);
        }
    }

    const size_t rowBase = (size_t)blockIdx.y * 128 + warp_m + (lane >> 2);
    const int colBase = blockIdx.x * 128 + warp_n + (lane & 3) * 2;
    #pragma unroll
    for (int i = 0; i < 4; ++i) {
        #pragma unroll
        for (int j = 0; j < 4; ++j) {
            size_t m0 = rowBase + i * 16;
            int n0 = colBase + j * 8;
            float b0 = bias[n0], b1 = bias[n0 + 1];
            *(__half2*)(C + m0 * (size_t)N + n0) =
                __floats2half2_rn(acc[i][j][0] + b0, acc[i][j][1] + b1);
            *(__half2*)(C + (m0 + 8) * (size_t)N + n0) =
                __floats2half2_rn(acc[i][j][2] + b0, acc[i][j][3] + b1);
        }
    }
}

// ===== fused GEMM + bias + residual + LayerNorm (full 512-wide rows) ============
#define LNG_STAGE (8192 + 65536)
#define LNG_SMEM  (3 * LNG_STAGE)

template<int NCHUNK, bool RES_HALF, bool OUT_HALF>
__global__ __launch_bounds__(512) void ln_gemm_t(const __half* __restrict__ A,
                                                 const __half* __restrict__ Bt,
                                                 const float* __restrict__ bias,
                                                 const void* __restrict__ resid,
                                                 const float* __restrict__ gam,
                                                 const float* __restrict__ bet,
                                                 void* __restrict__ outp) {
    constexpr int K = NCHUNK * 64;
    extern __shared__ char smem[];
    const uint32_t sb = smem_u32(smem);
    const int tid  = threadIdx.x;
    const int lane = tid & 31;
    const int wid  = tid >> 5;
    const int warp_m = (wid & 1) * 32;
    const int wid_n  = wid >> 1;
    const int warp_n = wid_n * 64;
    const int l7 = lane & 7;
    const int a_row_base = warp_m + l7 + ((lane & 8) ? 8 : 0);
    const int a_cc_add = (lane & 16) ? 1 : 0;
    const int b_row_base = warp_n + l7 + ((lane & 16) ? 8 : 0);
    const int b_cc_add = (lane & 8) ? 1 : 0;

    const size_t rowBlk = (size_t)blockIdx.x * 64;
    const __half* Abase = A + rowBlk * K;

    auto issue = [&](int t) {
        const int buf = t % 3;
        const uint32_t sA = sb + buf * LNG_STAGE;
        const uint32_t sB = sA + 8192;
        const __half* Ab = Abase + t * 64;
        const __half* Bb = Bt + t * 64;
        {
            int row = tid >> 3, cc = tid & 7;
            cp16(sA + row * 128 + ((cc ^ (row & 7)) << 4), Ab + (size_t)row * K + cc * 8);
        }
        #pragma unroll
        for (int ll = 0; ll < 8; ++ll) {
            int id = tid + ll * 512, row = id >> 3, cc = id & 7;
            cp16(sB + row * 128 + ((cc ^ (row & 7)) << 4), Bb + (size_t)row * K + cc * 8);
        }
        cp_commit();
    };

    float acc[2][8][4];
    #pragma unroll
    for (int i = 0; i < 2; ++i)
        #pragma unroll
        for (int j = 0; j < 8; ++j)
            #pragma unroll
            for (int q = 0; q < 4; ++q) acc[i][j][q] = 0.f;

    issue(0);
    issue(1);

    #pragma unroll 1
    for (int t = 0; t < NCHUNK; ++t) {
        if (t < NCHUNK - 1) cp_wait1(); else cp_wait0();
        __syncthreads();
        if (t + 2 < NCHUNK) issue(t + 2);

        const int buf = t % 3;
        const uint32_t sA = sb + buf * LNG_STAGE;
        const uint32_t sB = sA + 8192;

        #pragma unroll
        for (int q = 0; q < 4; ++q) {
            const int kc = 2 * q;
            uint32_t af[2][4], bf[4][4];
            #pragma unroll
            for (int i = 0; i < 2; ++i)
                ldsm4(af[i], sA + (uint32_t)(a_row_base + i * 16) * 128 +
                              (uint32_t)(((kc + a_cc_add) ^ l7) << 4));
            #pragma unroll
            for (int j2 = 0; j2 < 4; ++j2)
                ldsm4(bf[j2], sB + (uint32_t)(b_row_base + j2 * 16) * 128 +
                               (uint32_t)(((kc + b_cc_add) ^ l7) << 4));
            #pragma unroll
            for (int i = 0; i < 2; ++i)
                #pragma unroll
                for (int j = 0; j < 8; ++j)
                    mma_f16(acc[i][j], af[i], &bf[j >> 1][(j & 1) * 2]);
        }
    }
    __syncthreads();

    float2* red  = (float2*)smem;
    float2* stat = (float2*)(smem + 4096);
    const int rq = lane >> 2;
    const int cq = (lane & 3) * 2;

    #pragma unroll
    for (int i = 0; i < 2; ++i) {
        #pragma unroll
        for (int h2 = 0; h2 < 2; ++h2) {
            int row_local = warp_m + i * 16 + h2 * 8 + rq;
            size_t grow = (rowBlk + row_local) * 512;
            float s = 0.f, ss = 0.f;
            #pragma unroll
            for (int j = 0; j < 8; ++j) {
                int col = warp_n + cq + j * 8;
                float2 sv;
                if (RES_HALF)
                    sv = __half22float2(*(const __half2*)((const __half*)resid + grow + col));
                else
                    sv = *(const float2*)((const float*)resid + grow + col);
                float v0 = acc[i][j][h2 * 2 + 0] + bias[col]     + sv.x;
                float v1 = acc[i][j][h2 * 2 + 1] + bias[col + 1] + sv.y;
                acc[i][j][h2 * 2 + 0] = v0;
                acc[i][j][h2 * 2 + 1] = v1;
                s += v0 + v1;
                ss = fmaf(v0, v0, ss); ss = fmaf(v1, v1, ss);
            }
            s  += __shfl_xor_sync(0xffffffffu, s, 1);  s  += __shfl_xor_sync(0xffffffffu, s, 2);
            ss += __shfl_xor_sync(0xffffffffu, ss, 1); ss += __shfl_xor_sync(0xffffffffu, ss, 2);
            if ((lane & 3) == 0) red[row_local * 8 + wid_n] = make_float2(s, ss);
        }
    }
    __syncthreads();
    if (tid < 64) {
        float s = 0.f, ss = 0.f;
        #pragma unroll
        for (int w = 0; w < 8; ++w) {
            float2 v = red[tid * 8 + w];
            s += v.x; ss += v.y;
        }
        float mean = s * (1.0f / 512.0f);
        float var  = ss * (1.0f / 512.0f) - mean * mean;
        stat[tid] = make_float2(mean, rsqrtf(var + 1e-5f));
    }
    __syncthreads();
    #pragma unroll
    for (int i = 0; i < 2; ++i) {
        #pragma unroll
        for (int h2 = 0; h2 < 2; ++h2) {
            int row_local = warp_m + i * 16 + h2 * 8 + rq;
            float2 st = stat[row_local];
            size_t grow = (rowBlk + row_local) * 512;
            #pragma unroll
            for (int j = 0; j < 8; ++j) {
                int col = warp_n + cq + j * 8;
                float y0 = (acc[i][j][h2 * 2 + 0] - st.x) * st.y * gam[col]     + bet[col];
                float y1 = (acc[i][j][h2 * 2 + 1] - st.x) * st.y * gam[col + 1] + bet[col + 1];
                if (OUT_HALF)
                    *(__half2*)((__half*)outp + grow + col) = __floats2half2_rn(y0, y1);
                else
                    *(float2*)((float*)outp + grow + col) = make_float2(y0, y1);
            }
        }
    }
}

// ---------------- src -> half (float4 per thread, offset form) ------------------
__global__ void conv_src(const float* __restrict__ src, __half* __restrict__ dst, int n4) {
    int idx = blockIdx.x * blockDim.x + threadIdx.x;
    if (idx >= n4) return;
    float4 v = *(const float4*)(src + (size_t)idx * 4);
    __half2 a = __floats2half2_rn(v.x, v.y);
    __half2 b = __floats2half2_rn(v.z, v.w);
    uint2 w;
    w.x = *(uint32_t*)&a;
    w.y = *(uint32_t*)&b;
    *(uint2*)(dst + (size_t)idx * 4) = w;
}

// ---------------- weight packing ------------------------------------------------
__global__ void pack_qkv_w(const float* __restrict__ Wq, const float* __restrict__ Wk,
                           const float* __restrict__ Wv, const float* __restrict__ bq,
                           const float* __restrict__ bk, const float* __restrict__ bv) {
    int idx = blockIdx.x * blockDim.x + threadIdx.x;
    if (idx >= 512 * 1536) return;
    int d = idx / 1536, cc2 = idx % 1536;
    int sel = cc2 / 512, cc = cc2 % 512;
    int h = cc / 64, e = cc % 64;
    const float* W = (sel == 0) ? Wq : (sel == 1) ? Wk : Wv;
    g_Wqkv[(size_t)cc2 * 512 + d] = __float2half_rn(W[((size_t)h * 512 + d) * 64 + e]);
    if (d == 0) {
        const float* bb = (sel == 0) ? bq : (sel == 1) ? bk : bv;
        g_bqkv[cc2] = bb[cc];
    }
}

__global__ void pack_wo(const float* __restrict__ Wo) {
    int idx = blockIdx.x * blockDim.x + threadIdx.x;
    if (idx >= 512 * 512) return;
    int n = idx / 512, k = idx % 512;
    g_Wo_t[idx] = __float2half_rn(Wo[(size_t)k * 512 + n]);
}

__global__ void pack_wcat(const float* __restrict__ Wgcn) {
    int idx = blockIdx.x * blockDim.x + threadIdx.x;
    if (idx >= 512 * 1024) return;
    int n = idx / 1024, k = idx % 1024;
    float v;
    if (k < 512) v = Wgcn[(size_t)k * 512 + n] - Wgcn[262144 + (size_t)k * 512 + n];
    else         v = Wgcn[262144 + (size_t)(k - 512) * 512 + n];
    g_Wcat[idx] = __float2half_rn(v);
}

// ---------------- adjacency softmax ---------------------------------------------
__global__ void build_A(const int* __restrict__ rows, const int* __restrict__ cols,
                        const float* __restrict__ e, int nnz) {
    __shared__ float lg[NJ][NJ];
    int tid = threadIdx.x;
    if (tid < NJ * NJ) lg[tid / NJ][tid % NJ] = -9e15f;
    __syncthreads();
    if (tid < nnz) lg[rows[tid]][cols[tid]] = e[tid];
    __syncthreads();
    if (tid < NJ) {
        float m = -9e15f;
        #pragma unroll
        for (int k = 0; k < NJ; k++) m = fmaxf(m, lg[tid][k]);
        float ex[NJ]; float s = 0.f;
        #pragma unroll
        for (int k = 0; k < NJ; k++) { ex[k] = __expf(lg[tid][k] - m); s += ex[k]; }
        float inv = 1.0f / s;
        #pragma unroll
        for (int k = 0; k < NJ; k++) g_A[tid * NJ + k] = ex[k] * inv;
    }
}

// ---------------- attention via mma: one block per batch, warp per head ---------
// Q/K/V smem rows stride 260 u32 (=520 halves = 65*16B -> all ldmatrix phases
// conflict-free). S = Q K^T with M=32 (17 pad), N=24 (3xn8), K=64 (4xk16).
// Softmax on C-frags (cols >=17 masked), P re-packed as A-frags, O = P V with
// V B-frags via ldmatrix.x4.trans. O staged in smem (reusing Q) for coalesced out.
#define AQ_LD 260
#define ATTN_SMEM (3 * NJ * AQ_LD * 4)

__global__ __launch_bounds__(256) void attn_kernel(const __half* __restrict__ qkv,
                                                   __half* __restrict__ o) {
    extern __shared__ uint32_t sm[];
    uint32_t* qs = sm;
    uint32_t* ks = qs + NJ * AQ_LD;
    uint32_t* vs = ks + NJ * AQ_LD;
    const uint32_t qb  = smem_u32(qs);
    const uint32_t kbs = smem_u32(ks);
    const uint32_t vbs = smem_u32(vs);

    const int b = blockIdx.x, tid = threadIdx.x;
    const uint32_t* base = (const uint32_t*)(qkv + (size_t)b * NJ * 1536);
    for (int i = tid; i < NJ * 768; i += 256) {
        int row = i / 768, c = i % 768;
        uint32_t w = base[row * 768 + c];
        if (c < 256)      qs[row * AQ_LD + c]         = w;
        else if (c < 512) ks[row * AQ_LD + (c - 256)] = w;
        else              vs[row * AQ_LD + (c - 512)] = w;
    }
    __syncthreads();

    const int h = tid >> 5, lane = tid & 31;
    const int l4 = lane >> 2, c2 = (lane & 3) * 2;
    const int ecolh = h * 64;

    // ---- S = Q K^T ----
    float sa[2][3][4];
    #pragma unroll
    for (int m = 0; m < 2; ++m)
        #pragma unroll
        for (int n = 0; n < 3; ++n)
            #pragma unroll
            for (int q = 0; q < 4; ++q) sa[m][n][q] = 0.f;

    #pragma unroll
    for (int kb = 0; kb < 4; ++kb) {
        const int ec = ecolh + kb * 16;
        uint32_t qa[2][4];
        #pragma unroll
        for (int m = 0; m < 2; ++m) {
            int g = lane >> 3;
            int rr = m * 16 + (lane & 7) + ((g & 1) << 3);
            if (rr > 16) rr = 16;
            ldsm4(qa[m], qb + (uint32_t)rr * (AQ_LD * 4) +
                          (uint32_t)(ec + ((g & 2) ? 8 : 0)) * 2);
        }
        uint32_t kf[3][2];
        #pragma unroll
        for (int n = 0; n < 3; ++n) {
            int rr = n * 8 + (lane & 7);
            if (rr > 16) rr = 16;
            ldsm2(kf[n], kbs + (uint32_t)rr * (AQ_LD * 4) +
                          (uint32_t)(ec + ((lane & 8) ? 8 : 0)) * 2);
        }
        #pragma unroll
        for (int m = 0; m < 2; ++m)
            #pragma unroll
            for (int n = 0; n < 3; ++n)
                mma_f16(sa[m][n], qa[m], kf[n]);
    }

    // ---- softmax (rows spread across 4-lane groups; cols >=17 masked) ----
    uint32_t pf[2][2][4];
    #pragma unroll
    for (int m = 0; m < 2; ++m) {
        float slo[6], shi[6];
        #pragma unroll
        for (int n = 0; n < 3; ++n) {
            int col = n * 8 + c2;
            bool v0 = (col < 17), v1 = (col + 1 < 17);
            slo[2*n]   = v0 ? sa[m][n][0] * 0.125f : -1e30f;
            slo[2*n+1] = v1 ? sa[m][n][1] * 0.125f : -1e30f;
            shi[2*n]   = v0 ? sa[m][n][2] * 0.125f : -1e30f;
            shi[2*n+1] = v1 ? sa[m][n][3] * 0.125f : -1e30f;
        }
        float mlo = slo[0], mhi = shi[0];
        #pragma unroll
        for (int i = 1; i < 6; ++i) { mlo = fmaxf(mlo, slo[i]); mhi = fmaxf(mhi, shi[i]); }
        mlo = fmaxf(mlo, __shfl_xor_sync(0xffffffffu, mlo, 1));
        mlo = fmaxf(mlo, __shfl_xor_sync(0xffffffffu, mlo, 2));
        mhi = fmaxf(mhi, __shfl_xor_sync(0xffffffffu, mhi, 1));
        mhi = fmaxf(mhi, __shfl_xor_sync(0xffffffffu, mhi, 2));
        float plo[6], phi[6], sl = 0.f, sh = 0.f;
        #pragma unroll
        for (int i = 0; i < 6; ++i) {
            plo[i] = __expf(slo[i] - mlo); sl += plo[i];
            phi[i] = __expf(shi[i] - mhi); sh += phi[i];
        }
        sl += __shfl_xor_sync(0xffffffffu, sl, 1);
        sl += __shfl_xor_sync(0xffffffffu, sl, 2);
        sh += __shfl_xor_sync(0xffffffffu, sh, 1);
        sh += __shfl_xor_sync(0xffffffffu, sh, 2);
        float rl = 1.0f / sl, rh = 1.0f / sh;
        __half2 t0 = __floats2half2_rn(plo[0] * rl, plo[1] * rl);
        __half2 t1 = __floats2half2_rn(phi[0] * rh, phi[1] * rh);
        __half2 t2 = __floats2half2_rn(plo[2] * rl, plo[3] * rl);
        __half2 t3 = __floats2half2_rn(phi[2] * rh, phi[3] * rh);
        __half2 t4 = __floats2half2_rn(plo[4] * rl, plo[5] * rl);
        __half2 t5 = __floats2half2_rn(phi[4] * rh, phi[5] * rh);
        pf[m][0][0] = *(uint32_t*)&t0; pf[m][0][1] = *(uint32_t*)&t1;
        pf[m][0][2] = *(uint32_t*)&t2; pf[m][0][3] = *(uint32_t*)&t3;
        pf[m][1][0] = *(uint32_t*)&t4; pf[m][1][1] = *(uint32_t*)&t5;
        pf[m][1][2] = 0u;              pf[m][1][3] = 0u;
    }

    __syncthreads();                 // all warps done with qs/ks -> reuse qs
    uint32_t* ostage = qs;

    // ---- O = P V ----
    #pragma unroll
    for (int eb = 0; eb < 8; ++eb) {
        int rr = lane; if (rr > 16) rr = 16;
        uint32_t vf[4];
        ldsm4t(vf, vbs + (uint32_t)rr * (AQ_LD * 4) +
                    (uint32_t)(ecolh + eb * 8) * 2);
        const int cidx = (ecolh + eb * 8 + c2) >> 1;
        #pragma unroll
        for (int m = 0; m < 2; ++m) {
            float od[4] = {0.f, 0.f, 0.f, 0.f};
            mma_f16(od, pf[m][0], vf);
            mma_f16(od, pf[m][1], vf + 2);
            int r0 = m * 16 + l4;
            if (r0 < NJ) {
                __half2 w = __floats2half2_rn(od[0], od[1]);
                ostage[r0 * AQ_LD + cidx] = *(uint32_t*)&w;
            }
            if (r0 + 8 < NJ) {
                __half2 w = __floats2half2_rn(od[2], od[3]);
                ostage[(r0 + 8) * AQ_LD + cidx] = *(uint32_t*)&w;
            }
        }
    }
    __syncthreads();

    uint32_t* og = (uint32_t*)(o + (size_t)b * NJ * 512);
    for (int i = tid; i < NJ * 256; i += 256) {
        int row = i >> 8, c = i & 255;
        og[row * 256 + c] = ostage[row * AQ_LD + c];
    }
}

// ---------------- premix: u_j = [A_jj*x_j ; sum_k A_jk*x_k] ---------------------
__global__ __launch_bounds__(544) void premix(const __half* __restrict__ x,
                                              __half* __restrict__ u) {
    int b = blockIdx.x;
    __shared__ float xs[NJ][512];
    __shared__ float Arow[NJ][NJ];
    __shared__ float Ad[NJ];
    int tid = threadIdx.y * 32 + threadIdx.x;
    for (int i = tid; i < NJ * 256; i += 544) {
        int k = i >> 8, e2 = i & 255;
        float2 v = __half22float2(*(const __half2*)(x + ((size_t)(b * NJ + k)) * 512 + e2 * 2));
        xs[k][e2 * 2] = v.x; xs[k][e2 * 2 + 1] = v.y;
    }
    if (tid < NJ * NJ) {
        int j = tid / NJ, k = tid % NJ;
        float a = g_A[tid];
        Arow[j][k] = a;
        if (j == k) Ad[j] = a;
    }
    __syncthreads();

    int j = threadIdx.y, lane = threadIdx.x;
    __half* ur = u + ((size_t)(b * NJ + j)) * 1024;
    float adiag = Ad[j];
    #pragma unroll
    for (int t = 0; t < 16; t++) {
        int d = lane + (t << 5);
        float z = 0.f;
        #pragma unroll
        for (int k = 0; k < NJ; k++) z = fmaf(Arow[j][k], xs[k][d], z);
        ur[d]       = __float2half_rn(adiag * xs[j][d]);
        ur[512 + d] = __float2half_rn(z);
    }
}

// ---------------- host launcher --------------------------------------------------
extern "C" void kernel_launch(void* const* d_in, const int* in_sizes, int n_in,
                              void* d_out, int out_size) {
    const float* src   = (const float*)d_in[0];
    const float* Wq    = (const float*)d_in[1];
    const float* bq    = (const float*)d_in[2];
    const float* Wk    = (const float*)d_in[3];
    const float* bk    = (const float*)d_in[4];
    const float* Wv    = (const float*)d_in[5];
    const float* bv    = (const float*)d_in[6];
    const float* Wo    = (const float*)d_in[7];
    const float* bo    = (const float*)d_in[8];
    const float* ln1_g = (const float*)d_in[9];
    const float* ln1_b = (const float*)d_in[10];
    const float* Wgcn  = (const float*)d_in[11];
    const float* egcn  = (const float*)d_in[12];
    const float* bgcn  = (const float*)d_in[13];
    const float* ln2_g = (const float*)d_in[14];
    const float* ln2_b = (const float*)d_in[15];
    const int*   mrows = (const int*)d_in[16];
    const int*   mcols = (const int*)d_in[17];
    int nnz = in_sizes[16];
    float* out = (float*)d_out;

    __half *p_srch, *p_qkv, *p_o, *p_xh, *p_u, *p_Wqkv, *p_Wot, *p_Wcat;
    float *p_bqkv;
    cudaGetSymbolAddress((void**)&p_srch, g_src_h);
    cudaGetSymbolAddress((void**)&p_qkv,  g_qkv);
    cudaGetSymbolAddress((void**)&p_o,    g_o);
    cudaGetSymbolAddress((void**)&p_xh,   g_x_h);
    cudaGetSymbolAddress((void**)&p_u,    g_u);
    cudaGetSymbolAddress((void**)&p_Wqkv, g_Wqkv);
    cudaGetSymbolAddress((void**)&p_bqkv, g_bqkv);
    cudaGetSymbolAddress((void**)&p_Wot,  g_Wo_t);
    cudaGetSymbolAddress((void**)&p_Wcat, g_Wcat);

    static cudaStream_t s_side = nullptr, s_side2 = nullptr, s_c1 = nullptr;
    static cudaEvent_t e_fork = nullptr, e_join = nullptr, e_join2 = nullptr;
    static cudaEvent_t e_f1 = nullptr, e_f2 = nullptr, e_f3 = nullptr;
    if (!s_side) {
        cudaStreamCreateWithFlags(&s_side, cudaStreamNonBlocking);
        cudaStreamCreateWithFlags(&s_side2, cudaStreamNonBlocking);
        cudaStreamCreateWithFlags(&s_c1, cudaStreamNonBlocking);
        cudaEventCreateWithFlags(&e_fork, cudaEventDisableTiming);
        cudaEventCreateWithFlags(&e_join, cudaEventDisableTiming);
        cudaEventCreateWithFlags(&e_join2, cudaEventDisableTiming);
        cudaEventCreateWithFlags(&e_f1, cudaEventDisableTiming);
        cudaEventCreateWithFlags(&e_f2, cudaEventDisableTiming);
        cudaEventCreateWithFlags(&e_f3, cudaEventDisableTiming);
        cudaFuncSetAttribute(tc_gemm, cudaFuncAttributeMaxDynamicSharedMemorySize, GEMM_SMEM);
        cudaFuncSetAttribute(ln_gemm_t<8,  false, true >, cudaFuncAttributeMaxDynamicSharedMemorySize, LNG_SMEM);
        cudaFuncSetAttribute(ln_gemm_t<16, true,  false>, cudaFuncAttributeMaxDynamicSharedMemorySize, LNG_SMEM);
        cudaFuncSetAttribute(attn_kernel, cudaFuncAttributeMaxDynamicSharedMemorySize, ATTN_SMEM);
    }

    // ---- fork: packing on the two side streams
    cudaEventRecord(e_fork, 0);
    cudaStreamWaitEvent(s_side, e_fork, 0);
    cudaStreamWaitEvent(s_side2, e_fork, 0);
    cudaStreamWaitEvent(s_c1, e_fork, 0);
    pack_wo<<<(512 * 512 + 255) / 256, 256, 0, s_side>>>(Wo);
    pack_wcat<<<(512 * 1024 + 255) / 256, 256, 0, s_side>>>(Wgcn);
    build_A<<<1, 512, 0, s_side>>>(mrows, mcols, egcn, nnz);
    cudaEventRecord(e_join, s_side);

    pack_qkv_w<<<(512 * 1536 + 255) / 256, 256, 0, s_side2>>>(Wq, Wk, Wv, bq, bk, bv);
    cudaEventRecord(e_join2, s_side2);

    // Chain->stream map: 0->default, 1->s_c1, 2->s_side, 3->s_side2.
    cudaStream_t chst[NCHAINS] = { (cudaStream_t)0, s_c1, s_side, s_side2 };

    for (int c = 0; c < NCHAINS; ++c) {
        cudaStream_t st = chst[c];
        const size_t r0 = (size_t)c * CH_ROWS;
        const float*  srcH  = src    + r0 * 512;
        __half*       srchH = p_srch + r0 * 512;
        __half*       qkvH  = p_qkv  + r0 * 1536;
        __half*       oH    = p_o    + r0 * 512;
        __half*       xhH   = p_xh   + r0 * 512;
        __half*       uH    = p_u    + r0 * 1024;
        float*        outH  = out    + r0 * 512;

        conv_src<<<(CH_ROWS * 128 + 255) / 256, 256, 0, st>>>(srcH, srchH, CH_ROWS * 128);
        if (st != s_side2) cudaStreamWaitEvent(st, e_join2, 0);
        tc_gemm<<<dim3(1536 / 128, CH_ROWS / 128), 256, GEMM_SMEM, st>>>(srchH, p_Wqkv, p_bqkv, qkvH, 1536);
        attn_kernel<<<CH_B, 256, ATTN_SMEM, st>>>(qkvH, oH);
        if (st != s_side) cudaStreamWaitEvent(st, e_join, 0);
        ln_gemm_t<8, false, true><<<CH_ROWS / 64, 512, LNG_SMEM, st>>>(oH, p_Wot, bo, srcH, ln1_g, ln1_b, xhH);
        premix<<<CH_B, dim3(32, NJ), 0, st>>>(xhH, uH);
        ln_gemm_t<16, true, false><<<CH_ROWS / 64, 512, LNG_SMEM, st>>>(uH, p_Wcat, bgcn, xhH, ln2_g, ln2_b, outH);
    }

    // ---- join the three side chains back into the default stream
    cudaEventRecord(e_f1, s_c1);
    cudaEventRecord(e_f2, s_side);
    cudaEventRecord(e_f3, s_side2);
    cudaStreamWaitEvent(0, e_f1, 0);
    cudaStreamWaitEvent(0, e_f2, 0);
    cudaStreamWaitEvent(0, e_f3, 0);
}